// round 3
// baseline (speedup 1.0000x reference)
#include <cuda_runtime.h>

// LocallyConnected1d: out[b,o,l] = sum_{c,k} x[b,c,l+k] * w[o,c,l,k] + bias[o,l]
// B=32, Cin=128, Cout=128, L=2048, K=3, stride=1, W=2050. All fp32.

#define B_SZ   32
#define CIN    128
#define COUT   128
#define LOUT   2048
#define KW     3
#define WIN    2050

#define L_TILE 32
#define O_TILE 16
#define CC     8            // Cin chunk per smem stage
#define NTHREADS 256

#define XS_ROWS  (L_TILE + KW - 1)            // 34 w-positions
#define XS_ROW   36                           // padded b-dim (conflict-free LDS.128)
#define XS_FLOATS (CC * XS_ROWS * XS_ROW)     // 8*34*36 = 9792
#define WS_FLOATS (CC * O_TILE * (L_TILE*KW)) // 8*16*96 = 12288
#define SMEM_BYTES ((XS_FLOATS + WS_FLOATS) * 4)  // 88320 B

typedef unsigned long long u64;

static __device__ __forceinline__ u64 pack_dup(float a) {
    u64 r;
    asm("mov.b64 %0, {%1, %1};" : "=l"(r) : "f"(a));
    return r;
}
static __device__ __forceinline__ void unpack2(u64 v, float& a, float& b) {
    asm("mov.b64 {%0, %1}, %2;" : "=f"(a), "=f"(b) : "l"(v));
}
// Packed fp32x2 FMA (sm_100+): d = a*b + d elementwise on two fp32 lanes.
static __device__ __forceinline__ void ffma2(u64& d, u64 a, u64 b) {
    asm("fma.rn.f32x2 %0, %1, %2, %0;" : "+l"(d) : "l"(a), "l"(b));
}

__global__ void __launch_bounds__(NTHREADS, 2)
lc1d_kernel(const float* __restrict__ x,
            const float* __restrict__ wgt,
            const float* __restrict__ bias,
            float* __restrict__ out)
{
    extern __shared__ float smem[];
    float* Xs = smem;                 // [CC][34][36]  (Xs[ci][w][b], b padded to 36)
    float* Ws = smem + XS_FLOATS;     // [CC][O_TILE][96]  (j = lane*3 + k, contiguous)

    const int tid  = threadIdx.x;
    const int lane = tid & 31;        // lane == local l index
    const int warp = tid >> 5;
    const int b0   = (warp & 3) * 8;  // 4 warps cover b = 0..31 in groups of 8
    const int og   = (warp >> 2) * 8; // 2 warp-halves cover o-tile in groups of 8
    const int l0   = blockIdx.x * L_TILE;
    const int o0   = blockIdx.y * O_TILE;

    u64 acc[4][8];                    // [b-pair][o] packed f32x2 accumulators
    #pragma unroll
    for (int p = 0; p < 4; p++)
        #pragma unroll
        for (int o = 0; o < 8; o++) acc[p][o] = 0ull;

    for (int c0 = 0; c0 < CIN; c0 += CC) {
        __syncthreads();

        // ---- Load X tile: Xs[ci][w][b] = x[b, c0+ci, l0+w], w in [0,34) ----
        // Global reads are w-contiguous (coalesced); STS is conflict-free
        // (stride 36 floats => lanes 0..7 cover all 32 banks in vec phases).
        #pragma unroll
        for (int t = 0; t < (CC*32*XS_ROWS)/NTHREADS; t++) {   // 8704/256 = 34 exact
            int idx = tid + t*NTHREADS;
            int ci = idx / (32*XS_ROWS);
            int r  = idx - ci*(32*XS_ROWS);
            int b  = r / XS_ROWS;
            int w  = r - b*XS_ROWS;
            Xs[(ci*XS_ROWS + w)*XS_ROW + b] =
                x[(b*CIN + c0 + ci)*WIN + l0 + w];
        }

        // ---- Load W tile: Ws[ci][oi][j], j = (l-lane)*3 + k, 96 contiguous ----
        // Global reads fully coalesced (96-float contiguous runs).
        #pragma unroll
        for (int t = 0; t < WS_FLOATS/NTHREADS; t++) {         // 12288/256 = 48 exact
            int idx = tid + t*NTHREADS;
            int ci = idx / (O_TILE*96);
            int r  = idx - ci*(O_TILE*96);
            int oi = r / 96;
            int j  = r - oi*96;
            Ws[(ci*O_TILE + oi)*96 + j] =
                wgt[((o0 + oi)*CIN + c0 + ci)*(LOUT*KW) + l0*KW + j];
        }
        __syncthreads();

        // ---- Compute: per (ci,k): 8 b (2x LDS.128, pre-packed pairs) x 8 o ----
        #pragma unroll
        for (int ci = 0; ci < CC; ci++) {
            #pragma unroll
            for (int k = 0; k < KW; k++) {
                const float* xrow = &Xs[(ci*XS_ROWS + lane + k)*XS_ROW + b0];
                ulonglong2 xv0 = *reinterpret_cast<const ulonglong2*>(xrow);
                ulonglong2 xv1 = *reinterpret_cast<const ulonglong2*>(xrow + 4);
                const u64 px0 = xv0.x, px1 = xv0.y, px2 = xv1.x, px3 = xv1.y;
                // lane*3 + k: stride 3 coprime with 32 banks -> conflict-free
                const float* wp = &Ws[(ci*O_TILE + og)*96 + lane*KW + k];
                #pragma unroll
                for (int oi = 0; oi < 8; oi++) {
                    u64 wv = pack_dup(wp[oi*96]);
                    ffma2(acc[0][oi], px0, wv);
                    ffma2(acc[1][oi], px1, wv);
                    ffma2(acc[2][oi], px2, wv);
                    ffma2(acc[3][oi], px3, wv);
                }
            }
        }
    }

    // ---- Epilogue: add bias, store (l-contiguous => coalesced) ----
    #pragma unroll
    for (int oi = 0; oi < 8; oi++) {
        int o = o0 + og + oi;
        float bv = bias[o*LOUT + l0 + lane];
        #pragma unroll
        for (int p = 0; p < 4; p++) {
            float f0, f1;
            unpack2(acc[p][oi], f0, f1);
            int b = b0 + 2*p;
            out[(b*COUT + o)*LOUT + l0 + lane]       = f0 + bv;
            out[((b+1)*COUT + o)*LOUT + l0 + lane]   = f1 + bv;
        }
    }
}

extern "C" void kernel_launch(void* const* d_in, const int* in_sizes, int n_in,
                              void* d_out, int out_size)
{
    const float* x    = (const float*)d_in[0];
    const float* wgt  = (const float*)d_in[1];
    const float* bias = (const float*)d_in[2];
    float* out        = (float*)d_out;

    cudaFuncSetAttribute(lc1d_kernel,
                         cudaFuncAttributeMaxDynamicSharedMemorySize, SMEM_BYTES);

    dim3 grid(LOUT / L_TILE, COUT / O_TILE);   // (64, 8) = 512 blocks
    lc1d_kernel<<<grid, NTHREADS, SMEM_BYTES>>>(x, wgt, bias, out);
}

// round 5
// speedup vs baseline: 1.2156x; 1.2156x over previous
#include <cuda_runtime.h>
#include <cstdint>

// LocallyConnected1d: out[b,o,l] = sum_{c,k} x[b,c,l+k]*w[o,c,l,k] + bias[o,l]
// B=32, Cin=128, Cout=128, L=2048, K=3, S=1, W=2050, fp32.
//
// f32x2 packed-FMA compute (b-pairs), double-buffered cp.async pipeline
// over Cin chunks of 4. X stored pre-packed as float2 (b-pair innermost)
// so shared loads are conflict-free LDS.64 and fills are pure cp.async.

#define CIN     128
#define COUT    128
#define LOUT    2048
#define KW      3
#define WIN     2050

#define L_TILE  32
#define O_TILE  16
#define CC      4                     // Cin per pipeline stage
#define NST     (CIN / CC)            // 32 stages
#define NTHREADS 256

#define XPAD    34                    // float2 per (ci,bp) row: w in [0,34)
#define STAGE_X (CC * 16 * XPAD * 2)  // floats: 4*16*34*2 = 4352
#define STAGE_W (CC * O_TILE * (L_TILE * KW)) // 4*16*96 = 6144
#define STAGE_F (STAGE_X + STAGE_W)   // 10496 floats = 41984 B
#define SMEM_BYTES (2 * STAGE_F * 4)  // 83968 B -> 2 blocks/SM

typedef unsigned long long u64;

static __device__ __forceinline__ u64 pack_dup(float a) {
    u64 r; asm("mov.b64 %0, {%1, %1};" : "=l"(r) : "f"(a)); return r;
}
static __device__ __forceinline__ void unpack2(u64 v, float& a, float& b) {
    asm("mov.b64 {%0, %1}, %2;" : "=f"(a), "=f"(b) : "l"(v));
}
static __device__ __forceinline__ void ffma2(u64& d, u64 a, u64 b) {
    asm("fma.rn.f32x2 %0, %1, %2, %0;" : "+l"(d) : "l"(a), "l"(b));
}
static __device__ __forceinline__ unsigned smem_u32(const void* p) {
    unsigned r;
    asm("{ .reg .u64 t; cvta.to.shared.u64 t, %1; cvt.u32.u64 %0, t; }"
        : "=r"(r) : "l"(p));
    return r;
}
static __device__ __forceinline__ void cpa4(unsigned d, const float* s) {
    asm volatile("cp.async.ca.shared.global [%0], [%1], 4;" :: "r"(d), "l"(s));
}
static __device__ __forceinline__ void cpa16(unsigned d, const float* s) {
    asm volatile("cp.async.cg.shared.global [%0], [%1], 16;" :: "r"(d), "l"(s));
}
#define CP_COMMIT() asm volatile("cp.async.commit_group;" ::: "memory")
#define CP_WAIT0()  asm volatile("cp.async.wait_group 0;" ::: "memory")

// Fill stage s into buffer `buf`.
// X: 4352 floats, 17x cp.async 4B/thread. dst float offset:
//    ((ci*16 + b/2)*XPAD + w)*2 + (b&1)  — b-pair packed innermost.
// W: 6144 floats, 6x cp.async 16B/thread (.cg, stream-once).
static __device__ __forceinline__ void issue_load(
    const float* __restrict__ x, const float* __restrict__ wgt,
    unsigned smem_base, int buf, int s, int tid, int l0, int o0)
{
    const int c0 = s * CC;
    const unsigned xdst0 = smem_base + (unsigned)(buf * STAGE_F) * 4u;
    const unsigned wdst0 = xdst0 + STAGE_X * 4u;

    #pragma unroll
    for (int i = 0; i < 17; i++) {            // 17*256 = 4352 = CC*32*34
        int e  = i * NTHREADS + tid;
        int r  = e / 34;                       // (ci,b) row
        int w  = e - r * 34;
        int ci = r >> 5;
        int b  = r & 31;
        const float* src = x + (b * CIN + c0 + ci) * WIN + l0 + w;
        unsigned dst = xdst0 +
            (unsigned)((((ci * 16 + (b >> 1)) * XPAD + w) << 1) + (b & 1)) * 4u;
        cpa4(dst, src);
    }
    #pragma unroll
    for (int t = 0; t < 6; t++) {             // 6*256 float4 = 6144 floats
        int f   = t * NTHREADS + tid;
        int row = f / 24;                      // (ci,oi): 24 float4 per row
        int rem = f - row * 24;
        int ci  = row >> 4;
        int oi  = row & 15;
        const float* src = wgt + ((o0 + oi) * CIN + c0 + ci) * (LOUT * KW)
                               + l0 * KW + rem * 4;
        unsigned dst = wdst0 +
            (unsigned)((ci * O_TILE + oi) * 96 + rem * 4) * 4u;
        cpa16(dst, src);
    }
}

__global__ void __launch_bounds__(NTHREADS, 2)
lc1d_kernel(const float* __restrict__ x,
            const float* __restrict__ wgt,
            const float* __restrict__ bias,
            float* __restrict__ out)
{
    extern __shared__ float smem[];
    const unsigned smem_base = smem_u32(smem);

    const int tid  = threadIdx.x;
    const int lane = tid & 31;            // local l index
    const int warp = tid >> 5;
    const int bp0  = (warp & 3) * 4;      // b-pair group start
    const int og   = (warp >> 2) * 8;     // o group start within O_TILE
    const int l0   = blockIdx.x * L_TILE;
    const int o0   = blockIdx.y * O_TILE;

    u64 acc[4][8];
    #pragma unroll
    for (int p = 0; p < 4; p++)
        #pragma unroll
        for (int o = 0; o < 8; o++) acc[p][o] = 0ull;

    // prologue: prefetch stage 0 into buffer 0
    issue_load(x, wgt, smem_base, 0, 0, tid, l0, o0);
    CP_COMMIT();

    #pragma unroll 1
    for (int s = 0; s < NST; s++) {
        CP_WAIT0();                        // stage s data arrived (this thread)
        __syncthreads();                   // visible block-wide; prev buffer free

        // prefetch stage s+1 into the buffer compute(s-1) just released;
        // copies fly while compute(s) runs below
        if (s + 1 < NST) {
            issue_load(x, wgt, smem_base, (s + 1) & 1, s + 1, tid, l0, o0);
            CP_COMMIT();
        }

        const float* Xb = smem + (s & 1) * STAGE_F;
        const float* Wb = Xb + STAGE_X;

        #pragma unroll
        for (int ci = 0; ci < CC; ci++) {
            #pragma unroll
            for (int k = 0; k < KW; k++) {
                const u64* xp = reinterpret_cast<const u64*>(Xb)
                              + (ci * 16 + bp0) * XPAD + lane + k;
                const u64 px0 = xp[0];
                const u64 px1 = xp[XPAD];
                const u64 px2 = xp[2 * XPAD];
                const u64 px3 = xp[3 * XPAD];
                // lane*3+k addressing: stride 3 coprime with 32 banks
                const float* wp = Wb + (ci * O_TILE + og) * 96 + lane * KW + k;
                #pragma unroll
                for (int oi = 0; oi < 8; oi++) {
                    u64 wv = pack_dup(wp[oi * 96]);
                    ffma2(acc[0][oi], px0, wv);
                    ffma2(acc[1][oi], px1, wv);
                    ffma2(acc[2][oi], px2, wv);
                    ffma2(acc[3][oi], px3, wv);
                }
            }
        }
    }

    // epilogue: bias + coalesced stores (l-contiguous)
    const int b0 = (warp & 3) * 8;
    #pragma unroll
    for (int oi = 0; oi < 8; oi++) {
        int o = o0 + og + oi;
        float bv = bias[o * LOUT + l0 + lane];
        #pragma unroll
        for (int p = 0; p < 4; p++) {
            float f0, f1;
            unpack2(acc[p][oi], f0, f1);
            int b = b0 + 2 * p;
            out[(b * COUT + o) * LOUT + l0 + lane]       = f0 + bv;
            out[((b + 1) * COUT + o) * LOUT + l0 + lane] = f1 + bv;
        }
    }
}

extern "C" void kernel_launch(void* const* d_in, const int* in_sizes, int n_in,
                              void* d_out, int out_size)
{
    const float* x    = (const float*)d_in[0];
    const float* wgt  = (const float*)d_in[1];
    const float* bias = (const float*)d_in[2];
    float* out        = (float*)d_out;

    cudaFuncSetAttribute(lc1d_kernel,
                         cudaFuncAttributeMaxDynamicSharedMemorySize, SMEM_BYTES);

    dim3 grid(LOUT / L_TILE, COUT / O_TILE);   // (64, 8) = 512 blocks
    lc1d_kernel<<<grid, NTHREADS, SMEM_BYTES>>>(x, wgt, bias, out);
}